// round 1
// baseline (speedup 1.0000x reference)
#include <cuda_runtime.h>
#include <math.h>

#define BATCH 8
#define CH    512
#define CH3   1536
#define HH    64
#define NPIX  4096          // 64*64
#define WR    33            // rfft width 64/2+1
#define FREQ  2112          // 64*33
#define PLANES (BATCH*CH)   // 4096

// ---- static scratch (no allocations allowed) ----
__device__ float g_Xre[BATCH*CH*FREQ];
__device__ float g_Xim[BATCH*CH*FREQ];
__device__ float g_Qre[BATCH*CH3*FREQ];
__device__ float g_Qim[BATCH*CH3*FREQ];
__device__ float g_attn[BATCH*CH*NPIX];
__device__ float g_t[BATCH*CH*NPIX];

#define TWO_PI_OVER_64 0.09817477042468103f

// ============================================================
// Forward rfft2 of one 64x64 real plane (per block).
// out[kh*33+kw] = scale * sum_{h,w} p[h][w] e^{-2pi i (h kh + w kw)/64}
// ============================================================
__global__ __launch_bounds__(256) void fft2_fwd_kernel(
    const float* __restrict__ in,
    float* __restrict__ outre, float* __restrict__ outim,
    float scale)
{
    __shared__ float sp[HH][64];
    __shared__ float tre[HH][WR+1];
    __shared__ float tim[HH][WR+1];
    __shared__ float ct[64], st[64];
    const int tid = threadIdx.x;
    const int plane = blockIdx.x;
    const float* p = in + (size_t)plane * NPIX;

    if (tid < 64) {
        float s, c;
        sincosf(TWO_PI_OVER_64 * (float)tid, &s, &c);
        ct[tid] = c; st[tid] = s;
    }
    for (int i = tid; i < NPIX; i += 256) sp[i >> 6][i & 63] = p[i];
    __syncthreads();

    // Stage A: rfft along w (real input)
    for (int task = tid; task < FREQ; task += 256) {
        int h = task / WR, kw = task - h * WR;
        float ar = 0.f, ai = 0.f;
        #pragma unroll 16
        for (int w = 0; w < 64; w++) {
            float v = sp[h][w];
            int idx = (w * kw) & 63;
            ar += v * ct[idx];
            ai -= v * st[idx];
        }
        tre[h][kw] = ar; tim[h][kw] = ai;
    }
    __syncthreads();

    // Stage B: full complex FFT along h
    float* obr = outre + (size_t)plane * FREQ;
    float* obi = outim + (size_t)plane * FREQ;
    for (int task = tid; task < FREQ; task += 256) {
        int kh = task / WR, kw = task - kh * WR;
        float yr = 0.f, yi = 0.f;
        #pragma unroll 16
        for (int h = 0; h < 64; h++) {
            int idx = (h * kh) & 63;
            float c = ct[idx], s = st[idx];
            float ur = tre[h][kw], ui = tim[h][kw];
            yr += ur * c + ui * s;   // (ur+i ui)*(c - i s)
            yi += ui * c - ur * s;
        }
        obr[task] = yr * scale;
        obi[task] = yi * scale;
    }
}

// ============================================================
// Fused: Y = conj(a)*b elementwise, then irfft2 of Y (Hermitian),
// write real 64x64 plane. scale applied at the end.
// a plane offset: ((b*aCPB)+aOff+ch)*FREQ ; same for b-operand.
// ============================================================
__global__ __launch_bounds__(256) void prod_ifft2_kernel(
    const float* __restrict__ aRe, const float* __restrict__ aIm,
    int aCPB, int aOff,
    const float* __restrict__ bRe, const float* __restrict__ bIm,
    int bCPB, int bOff,
    float* __restrict__ out, float scale)
{
    __shared__ float yre[FREQ], yim[FREQ];
    __shared__ float ure[HH][WR+1], uim[HH][WR+1];
    __shared__ float ct[64], st[64];
    const int tid = threadIdx.x;
    const int plane = blockIdx.x;
    const int b  = plane >> 9;      // /512
    const int ch = plane & 511;
    const size_t oa = ((size_t)b * aCPB + aOff + ch) * FREQ;
    const size_t ob = ((size_t)b * bCPB + bOff + ch) * FREQ;

    if (tid < 64) {
        float s, c;
        sincosf(TWO_PI_OVER_64 * (float)tid, &s, &c);
        ct[tid] = c; st[tid] = s;
    }
    for (int i = tid; i < FREQ; i += 256) {
        float ar = aRe[oa + i], ai = aIm[oa + i];
        float br = bRe[ob + i], bi = bIm[ob + i];
        yre[i] = ar * br + ai * bi;   // conj(a)*b
        yim[i] = ar * bi - ai * br;
    }
    __syncthreads();

    // Stage A: inverse transform along kh: U[h][kw] = sum_kh Y e^{+2pi i h kh/64}
    for (int task = tid; task < FREQ; task += 256) {
        int h = task / WR, kw = task - h * WR;
        float ur = 0.f, ui = 0.f;
        #pragma unroll 16
        for (int kh = 0; kh < 64; kh++) {
            int idx = (h * kh) & 63;
            float c = ct[idx], s = st[idx];
            float yr = yre[kh * WR + kw], yi = yim[kh * WR + kw];
            ur += yr * c - yi * s;
            ui += yr * s + yi * c;
        }
        ure[h][kw] = ur; uim[h][kw] = ui;
    }
    __syncthreads();

    // Stage B: inverse along kw using Hermitian symmetry (take real part)
    float* op = out + (size_t)plane * NPIX;
    for (int task = tid; task < NPIX; task += 256) {
        int h = task >> 6, w = task & 63;
        float acc = ure[h][0];
        acc += (w & 1) ? -ure[h][32] : ure[h][32];
        float s2 = 0.f;
        #pragma unroll 16
        for (int kw = 1; kw < 32; kw++) {
            int idx = (w * kw) & 63;
            s2 += ure[h][kw] * ct[idx] - uim[h][kw] * st[idx];
        }
        op[task] = (acc + 2.f * s2) * scale;
    }
}

// ============================================================
// Per-plane softmax over 4096 elements, in-place.
// ============================================================
__global__ __launch_bounds__(256) void softmax_kernel(float* __restrict__ data)
{
    __shared__ float sh[NPIX];
    __shared__ float red[256];
    const int tid = threadIdx.x;
    float* p = data + (size_t)blockIdx.x * NPIX;

    float m = -3.4e38f;
    for (int i = tid; i < NPIX; i += 256) { float v = p[i]; sh[i] = v; m = fmaxf(m, v); }
    red[tid] = m; __syncthreads();
    for (int s = 128; s > 0; s >>= 1) { if (tid < s) red[tid] = fmaxf(red[tid], red[tid + s]); __syncthreads(); }
    const float M = red[0];
    __syncthreads();

    float sum = 0.f;
    for (int i = tid; i < NPIX; i += 256) { float e = __expf(sh[i] - M); sh[i] = e; sum += e; }
    red[tid] = sum; __syncthreads();
    for (int s = 128; s > 0; s >>= 1) { if (tid < s) red[tid] += red[tid + s]; __syncthreads(); }
    const float inv = 1.f / red[0];
    __syncthreads();

    for (int i = tid; i < NPIX; i += 256) p[i] = sh[i] * inv;
}

// ============================================================
// SIMT fp32 GEMM: C[m,n] = sum_k A[m,k] * B[k,n] (+epilogue)
//   A: M x K row-major (weight, shared across batch)
//   B: per-batch K x Ntot (n contiguous), batch stride K*Ntot
//   C: per-batch M x Ntot, batch stride M*Ntot
// 128x128x16 tile, 256 threads, 8x8 per thread (split 4+4).
// MODE 0: plain. MODE 1: bias + SiLU. MODE 2: B := B*B2 on load, bias.
// ============================================================
template<int MODE>
__global__ __launch_bounds__(256) void gemm_kernel(
    const float* __restrict__ A,
    const float* __restrict__ B,
    const float* __restrict__ B2,
    const float* __restrict__ bias,
    float* __restrict__ C,
    int M, int Ntot, int K)
{
    __shared__ float As[16][132];
    __shared__ float Bs[16][132];
    const int bx = blockIdx.x, by = blockIdx.y, bz = blockIdx.z;
    const float* Bp  = B  + (size_t)bz * K * Ntot;
    const float* B2p = (MODE == 2) ? (B2 + (size_t)bz * K * Ntot) : nullptr;
    float* Cp = C + (size_t)bz * M * Ntot;
    const int tid = threadIdx.x;
    const int n0 = bx * 128, m0 = by * 128;
    const int tx = tid & 15, ty = tid >> 4;

    const int arow = tid >> 2;            // 0..63
    const int acol = (tid & 3) * 4;       // 0,4,8,12
    const int brow = tid >> 5;            // 0..7
    const int bcol = (tid & 31) * 4;      // 0..124

    float acc[8][8];
    #pragma unroll
    for (int i = 0; i < 8; i++)
        #pragma unroll
        for (int j = 0; j < 8; j++) acc[i][j] = 0.f;

    for (int k0 = 0; k0 < K; k0 += 16) {
        #pragma unroll
        for (int r = 0; r < 2; r++) {
            float4 v = *(const float4*)&A[(size_t)(m0 + arow + r * 64) * K + k0 + acol];
            As[acol + 0][arow + r * 64] = v.x;
            As[acol + 1][arow + r * 64] = v.y;
            As[acol + 2][arow + r * 64] = v.z;
            As[acol + 3][arow + r * 64] = v.w;
        }
        #pragma unroll
        for (int r = 0; r < 2; r++) {
            int kk = brow + r * 8;
            int n  = n0 + bcol;
            float4 v = make_float4(0.f, 0.f, 0.f, 0.f);
            if (n < Ntot) {
                v = *(const float4*)&Bp[(size_t)(k0 + kk) * Ntot + n];
                if (MODE == 2) {
                    float4 g = *(const float4*)&B2p[(size_t)(k0 + kk) * Ntot + n];
                    v.x *= g.x; v.y *= g.y; v.z *= g.z; v.w *= g.w;
                }
            }
            *(float4*)&Bs[kk][bcol] = v;
        }
        __syncthreads();

        #pragma unroll
        for (int kk = 0; kk < 16; kk++) {
            float4 a0 = *(const float4*)&As[kk][ty * 4];
            float4 a1 = *(const float4*)&As[kk][64 + ty * 4];
            float4 b0 = *(const float4*)&Bs[kk][tx * 4];
            float4 b1 = *(const float4*)&Bs[kk][64 + tx * 4];
            float a[8] = {a0.x, a0.y, a0.z, a0.w, a1.x, a1.y, a1.z, a1.w};
            float b[8] = {b0.x, b0.y, b0.z, b0.w, b1.x, b1.y, b1.z, b1.w};
            #pragma unroll
            for (int i = 0; i < 8; i++)
                #pragma unroll
                for (int j = 0; j < 8; j++)
                    acc[i][j] += a[i] * b[j];
        }
        __syncthreads();
    }

    #pragma unroll
    for (int i = 0; i < 8; i++) {
        int m = m0 + ((i < 4) ? (ty * 4 + i) : (64 + ty * 4 + i - 4));
        float bv = (MODE >= 1) ? bias[m] : 0.f;
        #pragma unroll
        for (int j = 0; j < 8; j++) {
            int n = n0 + ((j < 4) ? (tx * 4 + j) : (64 + tx * 4 + j - 4));
            if (n < Ntot) {
                float v = acc[i][j] + bv;
                if (MODE == 1) v = v / (1.f + __expf(-v));   // SiLU
                Cp[(size_t)m * Ntot + n] = v;
            }
        }
    }
}

// ============================================================
extern "C" void kernel_launch(void* const* d_in, const int* in_sizes, int n_in,
                              void* d_out, int out_size)
{
    const float* x      = (const float*)d_in[0];
    const float* w_qkv  = (const float*)d_in[1];
    const float* w_gate = (const float*)d_in[2];
    const float* b_gate = (const float*)d_in[3];
    const float* w_proj = (const float*)d_in[4];
    const float* b_proj = (const float*)d_in[5];
    float* out = (float*)d_out;

    float *Xre, *Xim, *Qre, *Qim, *attn, *t;
    cudaGetSymbolAddress((void**)&Xre,  g_Xre);
    cudaGetSymbolAddress((void**)&Xim,  g_Xim);
    cudaGetSymbolAddress((void**)&Qre,  g_Qre);
    cudaGetSymbolAddress((void**)&Qim,  g_Qim);
    cudaGetSymbolAddress((void**)&attn, g_attn);
    cudaGetSymbolAddress((void**)&t,    g_t);

    const float inv64 = 1.0f / 64.0f;

    // 1. gate: t = SiLU(Wg * x + bg)     (b, 512, 4096)
    {
        dim3 g(4096 / 128, 512 / 128, BATCH);
        gemm_kernel<1><<<g, 256>>>(w_gate, x, nullptr, b_gate, t, 512, NPIX, 512);
    }
    // 2. X = rfft2(x), ortho (scale 1/64)
    fft2_fwd_kernel<<<PLANES, 256>>>(x, Xre, Xim, inv64);
    // 3. QKV = Wqkv * X  (re and im)
    {
        dim3 g((2112 + 127) / 128, 1536 / 128, BATCH);
        gemm_kernel<0><<<g, 256>>>(w_qkv, Xre, nullptr, nullptr, Qre, CH3, FREQ, 512);
        gemm_kernel<0><<<g, 256>>>(w_qkv, Xim, nullptr, nullptr, Qim, CH3, FREQ, 512);
    }
    // 4. attn = irfft2(conj(q)*k), ortho (scale 1/64)
    prod_ifft2_kernel<<<PLANES, 256>>>(Qre, Qim, CH3, 0,
                                       Qre, Qim, CH3, 512,
                                       attn, inv64);
    // 5. softmax over spatial positions, per (b,c)
    softmax_kernel<<<PLANES, 256>>>(attn);
    // 6. A = rfft2(attn), backward norm (scale 1) -> reuse X buffers
    fft2_fwd_kernel<<<PLANES, 256>>>(attn, Xre, Xim, 1.0f);
    // 7. y = irfft2(conj(A)*v), ortho (scale 1/64) -> reuse attn buffer
    prod_ifft2_kernel<<<PLANES, 256>>>(Xre, Xim, CH, 0,
                                       Qre, Qim, CH3, 1024,
                                       attn, inv64);
    // 8. out = Wp * (y .* t) + bp   -> directly (b, c, h, w)
    {
        dim3 g(4096 / 128, 512 / 128, BATCH);
        gemm_kernel<2><<<g, 256>>>(w_proj, attn, t, b_proj, out, 512, NPIX, 512);
    }
}

// round 2
// speedup vs baseline: 1.3167x; 1.3167x over previous
#include <cuda_runtime.h>
#include <math.h>

#define BATCH 8
#define CH    512
#define CH3   1536
#define HH    64
#define NPIX  4096          // 64*64
#define WR    33            // rfft width 64/2+1
#define FREQ  2112          // 64*33
#define PLANES (BATCH*CH)   // 4096

// ---- static scratch (no allocations allowed) ----
__device__ float g_Xre[BATCH*CH*FREQ];
__device__ float g_Xim[BATCH*CH*FREQ];
__device__ float g_Qre[BATCH*CH3*FREQ];
__device__ float g_Qim[BATCH*CH3*FREQ];
__device__ float g_attn[BATCH*CH*NPIX];
__device__ float g_t[BATCH*CH*NPIX];

#define TWO_PI_OVER_64 0.09817477042468103f

// ---- packed f32x2 helpers ----
typedef unsigned long long ull;

__device__ __forceinline__ ull pk2(float lo, float hi) {
    ull r;
    asm("mov.b64 %0, {%1, %2};" : "=l"(r) : "f"(lo), "f"(hi));
    return r;
}
__device__ __forceinline__ ull dup2(float v) { return pk2(v, v); }
__device__ __forceinline__ float2 upk2(ull v) {
    float2 f;
    asm("mov.b64 {%0, %1}, %2;" : "=f"(f.x), "=f"(f.y) : "l"(v));
    return f;
}
__device__ __forceinline__ void fma2(ull& d, ull a, ull b) {
    asm("fma.rn.f32x2 %0, %1, %2, %0;" : "+l"(d) : "l"(a), "l"(b));
}
__device__ __forceinline__ ull lds_u64(const float2* p) {
    return *reinterpret_cast<const ull*>(p);
}

// ============================================================
// Forward rfft2 of one 64x64 real plane (per block, 256 thr).
// out[kh*33+kw] = scale * sum_{h,w} p[h][w] e^{-2pi i (h kh + w kw)/64}
// ============================================================
__global__ __launch_bounds__(256) void fft2_fwd_kernel(
    const float* __restrict__ in,
    float* __restrict__ outre, float* __restrict__ outim,
    float scale)
{
    __shared__ float  sp[HH][65];
    __shared__ float2 t2[HH][WR];     // stage-A output, interleaved {re,im}
    __shared__ float2 TAf[64];        // {cos, -sin}
    __shared__ float2 TB1f[64];       // {cos, -sin}
    __shared__ float2 TB2f[64];       // {sin,  cos}
    const int tid = threadIdx.x;
    const float* p = in + (size_t)blockIdx.x * NPIX;

    if (tid < 64) {
        float s, c; sincosf(TWO_PI_OVER_64 * (float)tid, &s, &c);
        TAf[tid]  = make_float2(c, -s);
        TB1f[tid] = make_float2(c, -s);
        TB2f[tid] = make_float2(s,  c);
    }
    for (int i = tid; i < NPIX; i += 256) sp[i >> 6][i & 63] = p[i];
    __syncthreads();

    // ---- Stage A: transform along w. Tile: 2 h x 4 kw per thread (kw 0..31).
    {
        const int hg  = tid & 31;     // h = hg, hg+32
        const int kwg = tid >> 5;     // kw = 4*kwg + j
        ull acc0[4] = {0,0,0,0};      // {ar, ai} for h = hg
        ull acc1[4] = {0,0,0,0};      // for h = hg+32
        int idx[4], stp[4];
        #pragma unroll
        for (int j = 0; j < 4; j++) { idx[j] = 0; stp[j] = 4*kwg + j; }
        #pragma unroll 4
        for (int w = 0; w < 64; w++) {
            ull v0 = dup2(sp[hg][w]);
            ull v1 = dup2(sp[hg + 32][w]);
            #pragma unroll
            for (int j = 0; j < 4; j++) {
                ull T = lds_u64(&TAf[idx[j]]);     // broadcast within warp
                fma2(acc0[j], v0, T);
                fma2(acc1[j], v1, T);
                idx[j] = (idx[j] + stp[j]) & 63;
            }
        }
        #pragma unroll
        for (int j = 0; j < 4; j++) {
            t2[hg][4*kwg + j]      = upk2(acc0[j]);
            t2[hg + 32][4*kwg + j] = upk2(acc1[j]);
        }
        // kw = 32 (Nyquist): real alternating sum, imag = 0
        if (tid < 64) {
            float s = 0.f;
            #pragma unroll 8
            for (int w = 0; w < 64; w += 2) s += sp[tid][w] - sp[tid][w + 1];
            t2[tid][32] = make_float2(s, 0.f);
        }
    }
    __syncthreads();

    // ---- Stage B: transform along h. Tile: 2 kh x 4 kw per thread.
    {
        const int kwg = tid & 7;      // kw = 4*kwg + j   (8 idx per warp)
        const int khg = tid >> 3;     // kh = khg, khg+32 (4 per warp)
        ull acc0[4] = {0,0,0,0};      // {yr, yi} kh = khg
        ull acc1[4] = {0,0,0,0};      // kh = khg+32
        int idx = 0;                  // (h*khg) & 63
        #pragma unroll 4
        for (int h = 0; h < 64; h++) {
            int idx2 = idx ^ ((h & 1) << 5);   // (h*(khg+32)) & 63
            ull Ta1 = lds_u64(&TB1f[idx]);
            ull Ta2 = lds_u64(&TB2f[idx]);
            ull Tb1 = lds_u64(&TB1f[idx2]);
            ull Tb2 = lds_u64(&TB2f[idx2]);
            #pragma unroll
            for (int j = 0; j < 4; j++) {
                float2 u = t2[h][4*kwg + j];
                ull ud = dup2(u.x), vd = dup2(u.y);
                fma2(acc0[j], ud, Ta1); fma2(acc0[j], vd, Ta2);
                fma2(acc1[j], ud, Tb1); fma2(acc1[j], vd, Tb2);
            }
            idx = (idx + khg) & 63;
        }
        const size_t base = (size_t)blockIdx.x * FREQ;
        #pragma unroll
        for (int j = 0; j < 4; j++) {
            float2 r0 = upk2(acc0[j]);
            float2 r1 = upk2(acc1[j]);
            int n = 4*kwg + j;
            outre[base + khg*WR + n]        = r0.x * scale;
            outim[base + khg*WR + n]        = r0.y * scale;
            outre[base + (khg+32)*WR + n]   = r1.x * scale;
            outim[base + (khg+32)*WR + n]   = r1.y * scale;
        }
        // kw = 32 column: input real only
        if (tid < 64) {
            const int kh = tid;
            float yr = 0.f, yi = 0.f;
            int ix = 0;
            #pragma unroll 8
            for (int h = 0; h < 64; h++) {
                float2 T = TAf[ix];           // {c, -s}
                float tr = t2[h][32].x;
                yr = fmaf(tr, T.x, yr);
                yi = fmaf(tr, T.y, yi);
                ix = (ix + kh) & 63;
            }
            outre[base + kh*WR + 32] = yr * scale;
            outim[base + kh*WR + 32] = yi * scale;
        }
    }
}

// ============================================================
// Fused: Y = conj(a)*b elementwise, then irfft2 of Y (Hermitian),
// write real 64x64 plane, * scale.
// ============================================================
__global__ __launch_bounds__(256) void prod_ifft2_kernel(
    const float* __restrict__ aRe, const float* __restrict__ aIm,
    int aCPB, int aOff,
    const float* __restrict__ bRe, const float* __restrict__ bIm,
    int bCPB, int bOff,
    float* __restrict__ out, float scale)
{
    __shared__ float2 y2[FREQ];       // {yr, yi}
    __shared__ float2 u2[FREQ];       // {ur, ui}
    __shared__ float2 TI1f[64];       // {cos,  sin}
    __shared__ float2 TI2f[64];       // {-sin, cos}
    __shared__ float2 TSf[64];        // {cos,  sin} scalar use
    const int tid = threadIdx.x;
    const int plane = blockIdx.x;
    const int b  = plane >> 9;
    const int ch = plane & 511;
    const size_t oa = ((size_t)b * aCPB + aOff + ch) * FREQ;
    const size_t ob = ((size_t)b * bCPB + bOff + ch) * FREQ;

    if (tid < 64) {
        float s, c; sincosf(TWO_PI_OVER_64 * (float)tid, &s, &c);
        TI1f[tid] = make_float2(c,  s);
        TI2f[tid] = make_float2(-s, c);
        TSf[tid]  = make_float2(c,  s);
    }
    for (int i = tid; i < FREQ; i += 256) {
        float ar = aRe[oa + i], ai = aIm[oa + i];
        float br = bRe[ob + i], bi = bIm[ob + i];
        y2[i] = make_float2(ar*br + ai*bi, ar*bi - ai*br);   // conj(a)*b
    }
    __syncthreads();

    // ---- Stage A: inverse transform along kh. Tile: 2 h x 4 kw.
    {
        const int kwg = tid & 7;      // kw = 4*kwg + j
        const int hg  = tid >> 3;     // h = hg, hg+32
        ull acc0[4] = {0,0,0,0};      // {ur, ui} h = hg
        ull acc1[4] = {0,0,0,0};      // h = hg+32
        int idx = 0;                  // (hg*kh) & 63
        #pragma unroll 4
        for (int kh = 0; kh < 64; kh++) {
            int idx2 = idx ^ ((kh & 1) << 5);
            ull Ta1 = lds_u64(&TI1f[idx]);
            ull Ta2 = lds_u64(&TI2f[idx]);
            ull Tb1 = lds_u64(&TI1f[idx2]);
            ull Tb2 = lds_u64(&TI2f[idx2]);
            #pragma unroll
            for (int j = 0; j < 4; j++) {
                float2 y = y2[kh*WR + 4*kwg + j];
                ull yr = dup2(y.x), yi = dup2(y.y);
                fma2(acc0[j], yr, Ta1); fma2(acc0[j], yi, Ta2);
                fma2(acc1[j], yr, Tb1); fma2(acc1[j], yi, Tb2);
            }
            idx = (idx + hg) & 63;
        }
        #pragma unroll
        for (int j = 0; j < 4; j++) {
            u2[hg*WR + 4*kwg + j]        = upk2(acc0[j]);
            u2[(hg + 32)*WR + 4*kwg + j] = upk2(acc1[j]);
        }
        // kw = 32 column (full complex inverse DFT over kh)
        if (tid < 64) {
            const int h = tid;
            float ur = 0.f, ui = 0.f;
            int ix = 0;
            #pragma unroll 8
            for (int kh = 0; kh < 64; kh++) {
                float2 T = TSf[ix];           // {c, s}
                float2 y = y2[kh*WR + 32];
                ur = fmaf(y.x, T.x, fmaf(-y.y, T.y, ur));
                ui = fmaf(y.x, T.y, fmaf( y.y, T.x, ui));
                ix = (ix + h) & 63;
            }
            u2[h*WR + 32] = make_float2(ur, ui);
        }
    }
    __syncthreads();

    // ---- Stage B: inverse along kw (Hermitian, real out). Tile: 2 h x 4 wbase,
    // each wbase also produces w+32 via (-1)^kw symmetry.
    {
        const int wg = tid & 7;       // wbase = 4*wg + j
        const int hg = tid >> 3;      // h = hg, hg+32
        float accP[2][4] = {{0,0,0,0},{0,0,0,0}};   // sum t        -> w
        float accM[2][4] = {{0,0,0,0},{0,0,0,0}};   // sum (-1)^kw t -> w+32
        int idx[4], stp[4];
        #pragma unroll
        for (int j = 0; j < 4; j++) { stp[j] = 4*wg + j; idx[j] = stp[j]; } // kw=1
        #pragma unroll 2
        for (int kw = 1; kw < 32; kw++) {
            float sgn = (kw & 1) ? -1.f : 1.f;
            float2 ua = u2[hg*WR + kw];
            float2 ub = u2[(hg + 32)*WR + kw];
            #pragma unroll
            for (int j = 0; j < 4; j++) {
                float2 T = TSf[idx[j]];
                float ta = fmaf(ua.x, T.x, -ua.y * T.y);
                float tb = fmaf(ub.x, T.x, -ub.y * T.y);
                accP[0][j] += ta;  accM[0][j] = fmaf(sgn, ta, accM[0][j]);
                accP[1][j] += tb;  accM[1][j] = fmaf(sgn, tb, accM[1][j]);
                idx[j] = (idx[j] + stp[j]) & 63;
            }
        }
        float* op = out + (size_t)plane * NPIX;
        float dcA = u2[hg*WR].x,        nyA = u2[hg*WR + 32].x;
        float dcB = u2[(hg + 32)*WR].x, nyB = u2[(hg + 32)*WR + 32].x;
        #pragma unroll
        for (int j = 0; j < 4; j++) {
            int w = 4*wg + j;
            float ps = (j & 1) ? -1.f : 1.f;          // (-1)^w, w parity = j parity
            float baseA = fmaf(ps, nyA, dcA);
            float baseB = fmaf(ps, nyB, dcB);
            op[hg*64 + w]             = (2.f*accP[0][j] + baseA) * scale;
            op[hg*64 + w + 32]        = (2.f*accM[0][j] + baseA) * scale;
            op[(hg + 32)*64 + w]      = (2.f*accP[1][j] + baseB) * scale;
            op[(hg + 32)*64 + w + 32] = (2.f*accM[1][j] + baseB) * scale;
        }
    }
}

// ============================================================
// Per-plane softmax over 4096 elements, in-place.
// ============================================================
__global__ __launch_bounds__(256) void softmax_kernel(float* __restrict__ data)
{
    __shared__ float sh[NPIX];
    __shared__ float red[256];
    const int tid = threadIdx.x;
    float* p = data + (size_t)blockIdx.x * NPIX;

    float m = -3.4e38f;
    for (int i = tid; i < NPIX; i += 256) { float v = p[i]; sh[i] = v; m = fmaxf(m, v); }
    red[tid] = m; __syncthreads();
    for (int s = 128; s > 0; s >>= 1) { if (tid < s) red[tid] = fmaxf(red[tid], red[tid + s]); __syncthreads(); }
    const float M = red[0];
    __syncthreads();

    float sum = 0.f;
    for (int i = tid; i < NPIX; i += 256) { float e = __expf(sh[i] - M); sh[i] = e; sum += e; }
    red[tid] = sum; __syncthreads();
    for (int s = 128; s > 0; s >>= 1) { if (tid < s) red[tid] += red[tid + s]; __syncthreads(); }
    const float inv = 1.f / red[0];
    __syncthreads();

    for (int i = tid; i < NPIX; i += 256) p[i] = sh[i] * inv;
}

// ============================================================
// Packed-f32x2 SIMT GEMM: C[m,n] = sum_k A[m,k]*B[k,n] (+epilogue)
// 128x128x16 tile, 256 threads, 8x8 per thread via 32 FFMA2/kk.
// A-tile stored duplicated in smem -> LDS.128 yields {a,a} pairs.
// MODE 0: plain. MODE 1: bias + SiLU. MODE 2: B := B*B2 on load, bias.
// ============================================================
template<int MODE>
__global__ __launch_bounds__(256) void gemm_kernel(
    const float* __restrict__ A,
    const float* __restrict__ B,
    const float* __restrict__ B2,
    const float* __restrict__ bias,
    float* __restrict__ C,
    int M, int Ntot, int K)
{
    __shared__ float Asd[16][264];    // duplicated: Asd[k][2m]=Asd[k][2m+1]=A[m,k]
    __shared__ float Bs[16][132];
    const int bx = blockIdx.x, by = blockIdx.y, bz = blockIdx.z;
    const float* Bp  = B  + (size_t)bz * K * Ntot;
    const float* B2p = (MODE == 2) ? (B2 + (size_t)bz * K * Ntot) : nullptr;
    float* Cp = C + (size_t)bz * M * Ntot;
    const int tid = threadIdx.x;
    const int n0 = bx * 128, m0 = by * 128;
    const int tx = tid & 15, ty = tid >> 4;

    const int arow = tid >> 2;            // 0..63
    const int acol = (tid & 3) * 4;       // 0,4,8,12
    const int brow = tid >> 5;            // 0..7
    const int bcol = (tid & 31) * 4;      // 0..124

    ull acc[8][4];
    #pragma unroll
    for (int i = 0; i < 8; i++)
        #pragma unroll
        for (int j = 0; j < 4; j++) acc[i][j] = 0ull;

    for (int k0 = 0; k0 < K; k0 += 16) {
        #pragma unroll
        for (int r = 0; r < 2; r++) {
            float4 v = *(const float4*)&A[(size_t)(m0 + arow + r * 64) * K + k0 + acol];
            int cc = 2*arow + r*128;
            *(float2*)&Asd[acol + 0][cc] = make_float2(v.x, v.x);
            *(float2*)&Asd[acol + 1][cc] = make_float2(v.y, v.y);
            *(float2*)&Asd[acol + 2][cc] = make_float2(v.z, v.z);
            *(float2*)&Asd[acol + 3][cc] = make_float2(v.w, v.w);
        }
        #pragma unroll
        for (int r = 0; r < 2; r++) {
            int kk = brow + r * 8;
            int n  = n0 + bcol;
            float4 v = make_float4(0.f, 0.f, 0.f, 0.f);
            if (n < Ntot) {
                v = *(const float4*)&Bp[(size_t)(k0 + kk) * Ntot + n];
                if (MODE == 2) {
                    float4 g = *(const float4*)&B2p[(size_t)(k0 + kk) * Ntot + n];
                    v.x *= g.x; v.y *= g.y; v.z *= g.z; v.w *= g.w;
                }
            }
            *(float4*)&Bs[kk][bcol] = v;
        }
        __syncthreads();

        #pragma unroll
        for (int kk = 0; kk < 16; kk++) {
            ulonglong2 a01 = *(const ulonglong2*)&Asd[kk][8*ty];
            ulonglong2 a23 = *(const ulonglong2*)&Asd[kk][8*ty + 4];
            ulonglong2 a45 = *(const ulonglong2*)&Asd[kk][128 + 8*ty];
            ulonglong2 a67 = *(const ulonglong2*)&Asd[kk][128 + 8*ty + 4];
            ulonglong2 b01 = *(const ulonglong2*)&Bs[kk][4*tx];
            ulonglong2 b23 = *(const ulonglong2*)&Bs[kk][64 + 4*tx];
            ull a[8] = {a01.x, a01.y, a23.x, a23.y, a45.x, a45.y, a67.x, a67.y};
            ull bb[4] = {b01.x, b01.y, b23.x, b23.y};
            #pragma unroll
            for (int i = 0; i < 8; i++)
                #pragma unroll
                for (int j = 0; j < 4; j++)
                    fma2(acc[i][j], a[i], bb[j]);
        }
        __syncthreads();
    }

    #pragma unroll
    for (int i = 0; i < 8; i++) {
        int m = m0 + ((i < 4) ? (ty * 4 + i) : (64 + ty * 4 + i - 4));
        float bv = (MODE >= 1) ? bias[m] : 0.f;
        #pragma unroll
        for (int jp = 0; jp < 4; jp++) {
            float2 v2 = upk2(acc[i][jp]);
            int nbase = n0 + ((jp < 2) ? (tx * 4 + 2*jp) : (64 + tx * 4 + 2*(jp - 2)));
            float vx = v2.x + bv, vy = v2.y + bv;
            if (MODE == 1) {
                vx = vx / (1.f + __expf(-vx));
                vy = vy / (1.f + __expf(-vy));
            }
            if (nbase < Ntot)     Cp[(size_t)m * Ntot + nbase]     = vx;
            if (nbase + 1 < Ntot) Cp[(size_t)m * Ntot + nbase + 1] = vy;
        }
    }
}

// ============================================================
extern "C" void kernel_launch(void* const* d_in, const int* in_sizes, int n_in,
                              void* d_out, int out_size)
{
    const float* x      = (const float*)d_in[0];
    const float* w_qkv  = (const float*)d_in[1];
    const float* w_gate = (const float*)d_in[2];
    const float* b_gate = (const float*)d_in[3];
    const float* w_proj = (const float*)d_in[4];
    const float* b_proj = (const float*)d_in[5];
    float* out = (float*)d_out;

    float *Xre, *Xim, *Qre, *Qim, *attn, *t;
    cudaGetSymbolAddress((void**)&Xre,  g_Xre);
    cudaGetSymbolAddress((void**)&Xim,  g_Xim);
    cudaGetSymbolAddress((void**)&Qre,  g_Qre);
    cudaGetSymbolAddress((void**)&Qim,  g_Qim);
    cudaGetSymbolAddress((void**)&attn, g_attn);
    cudaGetSymbolAddress((void**)&t,    g_t);

    const float inv64 = 1.0f / 64.0f;

    // 1. gate: t = SiLU(Wg * x + bg)
    {
        dim3 g(4096 / 128, 512 / 128, BATCH);
        gemm_kernel<1><<<g, 256>>>(w_gate, x, nullptr, b_gate, t, 512, NPIX, 512);
    }
    // 2. X = rfft2(x), ortho
    fft2_fwd_kernel<<<PLANES, 256>>>(x, Xre, Xim, inv64);
    // 3. QKV = Wqkv * X (re, im)
    {
        dim3 g((FREQ + 127) / 128, CH3 / 128, BATCH);
        gemm_kernel<0><<<g, 256>>>(w_qkv, Xre, nullptr, nullptr, Qre, CH3, FREQ, 512);
        gemm_kernel<0><<<g, 256>>>(w_qkv, Xim, nullptr, nullptr, Qim, CH3, FREQ, 512);
    }
    // 4. attn = irfft2(conj(q)*k), ortho
    prod_ifft2_kernel<<<PLANES, 256>>>(Qre, Qim, CH3, 0,
                                       Qre, Qim, CH3, 512,
                                       attn, inv64);
    // 5. softmax over spatial positions
    softmax_kernel<<<PLANES, 256>>>(attn);
    // 6. A = rfft2(attn), backward norm (scale 1)
    fft2_fwd_kernel<<<PLANES, 256>>>(attn, Xre, Xim, 1.0f);
    // 7. y = irfft2(conj(A)*v), ortho
    prod_ifft2_kernel<<<PLANES, 256>>>(Xre, Xim, CH, 0,
                                       Qre, Qim, CH3, 1024,
                                       attn, inv64);
    // 8. out = Wp * (y .* t) + bp
    {
        dim3 g(4096 / 128, 512 / 128, BATCH);
        gemm_kernel<2><<<g, 256>>>(w_proj, attn, t, b_proj, out, 512, NPIX, 512);
    }
}

// round 4
// speedup vs baseline: 1.8035x; 1.3697x over previous
#include <cuda_runtime.h>
#include <cstdint>
#include <math.h>

#define BATCH 8
#define CH    512
#define CH3   1536
#define HH    64
#define NPIX  4096          // 64*64
#define WR    33            // rfft width 64/2+1
#define FREQ  2112          // 64*33
#define PLANES (BATCH*CH)   // 4096

// ---- static scratch (no allocations allowed) ----
__device__ float g_Xre[BATCH*CH*FREQ];
__device__ float g_Xim[BATCH*CH*FREQ];
__device__ float g_Qre[BATCH*CH3*FREQ];
__device__ float g_Qim[BATCH*CH3*FREQ];
__device__ float g_y[BATCH*CH*NPIX];
__device__ float g_t[BATCH*CH*NPIX];

#define TWO_PI_OVER_64 0.09817477042468103f

// ---- packed f32x2 helpers ----
typedef unsigned long long ull;

__device__ __forceinline__ ull pk2(float lo, float hi) {
    ull r;
    asm("mov.b64 %0, {%1, %2};" : "=l"(r) : "f"(lo), "f"(hi));
    return r;
}
__device__ __forceinline__ ull dup2(float v) { return pk2(v, v); }
__device__ __forceinline__ float2 upk2(ull v) {
    float2 f;
    asm("mov.b64 {%0, %1}, %2;" : "=f"(f.x), "=f"(f.y) : "l"(v));
    return f;
}
__device__ __forceinline__ void fma2(ull& d, ull a, ull b) {
    asm("fma.rn.f32x2 %0, %1, %2, %0;" : "+l"(d) : "l"(a), "l"(b));
}
__device__ __forceinline__ ull lds_u64(const float2* p) {
    return *reinterpret_cast<const ull*>(p);
}
__device__ __forceinline__ void cp_async16(unsigned int saddr, const void* g, int sz) {
    asm volatile("cp.async.cg.shared.global [%0], [%1], 16, %2;\n"
                 :: "r"(saddr), "l"(g), "r"(sz));
}
__device__ __forceinline__ void cp_commit() { asm volatile("cp.async.commit_group;\n"); }
__device__ __forceinline__ void cp_wait0()  { asm volatile("cp.async.wait_group 0;\n" ::: "memory"); }

// ============================================================
// Forward rfft2 of one 64x64 real plane (per block, 256 thr).
// ============================================================
__global__ __launch_bounds__(256) void fft2_fwd_kernel(
    const float* __restrict__ in,
    float* __restrict__ outre, float* __restrict__ outim,
    float scale)
{
    __shared__ float  sp[HH][65];
    __shared__ float2 t2[HH][WR];
    __shared__ float2 TAf[64];        // {cos, -sin}
    __shared__ float2 TB2f[64];       // {sin,  cos}
    const int tid = threadIdx.x;
    const float* p = in + (size_t)blockIdx.x * NPIX;

    if (tid < 64) {
        float s, c; sincosf(TWO_PI_OVER_64 * (float)tid, &s, &c);
        TAf[tid]  = make_float2(c, -s);
        TB2f[tid] = make_float2(s,  c);
    }
    for (int i = tid; i < NPIX; i += 256) sp[i >> 6][i & 63] = p[i];
    __syncthreads();

    // Stage A: transform along w. 2 h x 4 kw per thread (kw 0..31).
    {
        const int hg  = tid & 31;
        const int kwg = tid >> 5;
        ull acc0[4] = {0,0,0,0};
        ull acc1[4] = {0,0,0,0};
        int idx[4], stp[4];
        #pragma unroll
        for (int j = 0; j < 4; j++) { idx[j] = 0; stp[j] = 4*kwg + j; }
        #pragma unroll 4
        for (int w = 0; w < 64; w++) {
            ull v0 = dup2(sp[hg][w]);
            ull v1 = dup2(sp[hg + 32][w]);
            #pragma unroll
            for (int j = 0; j < 4; j++) {
                ull T = lds_u64(&TAf[idx[j]]);
                fma2(acc0[j], v0, T);
                fma2(acc1[j], v1, T);
                idx[j] = (idx[j] + stp[j]) & 63;
            }
        }
        #pragma unroll
        for (int j = 0; j < 4; j++) {
            t2[hg][4*kwg + j]      = upk2(acc0[j]);
            t2[hg + 32][4*kwg + j] = upk2(acc1[j]);
        }
        if (tid < 64) {
            float s = 0.f;
            #pragma unroll 8
            for (int w = 0; w < 64; w += 2) s += sp[tid][w] - sp[tid][w + 1];
            t2[tid][32] = make_float2(s, 0.f);
        }
    }
    __syncthreads();

    // Stage B: transform along h. 2 kh x 4 kw per thread.
    {
        const int kwg = tid & 7;
        const int khg = tid >> 3;
        ull acc0[4] = {0,0,0,0};
        ull acc1[4] = {0,0,0,0};
        int idx = 0;
        #pragma unroll 4
        for (int h = 0; h < 64; h++) {
            int idx2 = idx ^ ((h & 1) << 5);
            ull Ta1 = lds_u64(&TAf[idx]);
            ull Ta2 = lds_u64(&TB2f[idx]);
            ull Tb1 = lds_u64(&TAf[idx2]);
            ull Tb2 = lds_u64(&TB2f[idx2]);
            #pragma unroll
            for (int j = 0; j < 4; j++) {
                float2 u = t2[h][4*kwg + j];
                ull ud = dup2(u.x), vd = dup2(u.y);
                fma2(acc0[j], ud, Ta1); fma2(acc0[j], vd, Ta2);
                fma2(acc1[j], ud, Tb1); fma2(acc1[j], vd, Tb2);
            }
            idx = (idx + khg) & 63;
        }
        const size_t base = (size_t)blockIdx.x * FREQ;
        #pragma unroll
        for (int j = 0; j < 4; j++) {
            float2 r0 = upk2(acc0[j]);
            float2 r1 = upk2(acc1[j]);
            int n = 4*kwg + j;
            outre[base + khg*WR + n]      = r0.x * scale;
            outim[base + khg*WR + n]      = r0.y * scale;
            outre[base + (khg+32)*WR + n] = r1.x * scale;
            outim[base + (khg+32)*WR + n] = r1.y * scale;
        }
        if (tid < 64) {
            const int kh = tid;
            float yr = 0.f, yi = 0.f;
            int ix = 0;
            #pragma unroll 8
            for (int h = 0; h < 64; h++) {
                float2 T = TAf[ix];
                float tr = t2[h][32].x;
                yr = fmaf(tr, T.x, yr);
                yi = fmaf(tr, T.y, yi);
                ix = (ix + kh) & 63;
            }
            outre[base + kh*WR + 32] = yr * scale;
            outim[base + kh*WR + 32] = yi * scale;
        }
    }
}

// ============================================================
// Fused middle: attnF = conj(q)*k -> irfft2(ortho) -> softmax ->
// rfft2(backward norm) -> outre/outim. Plane never leaves smem.
// ============================================================
__global__ __launch_bounds__(256) void mid_fused_kernel(
    const float* __restrict__ qRe, const float* __restrict__ qIm,
    float* __restrict__ outre, float* __restrict__ outim)
{
    __shared__ float2 y2[FREQ];       // also reused as plane [64][65] floats
    __shared__ float2 u2[FREQ];       // also reused as fwd t2 [64][33]
    __shared__ float2 Tcs[64];        // {cos,  sin}
    __shared__ float2 Tns[64];        // {-sin, cos}
    __shared__ float2 Tcn[64];        // {cos, -sin}
    __shared__ float2 Tsc[64];        // {sin,  cos}
    __shared__ float  red[256];
    float* pl = (float*)y2;           // plane buffer, stride 65 (4160 <= 4224 floats)

    const int tid = threadIdx.x;
    const int plane = blockIdx.x;
    const int b  = plane >> 9;
    const int ch = plane & 511;
    const size_t oq = ((size_t)b * CH3 + ch) * FREQ;
    const size_t ok = ((size_t)b * CH3 + 512 + ch) * FREQ;

    if (tid < 64) {
        float s, c; sincosf(TWO_PI_OVER_64 * (float)tid, &s, &c);
        Tcs[tid] = make_float2(c,  s);
        Tns[tid] = make_float2(-s, c);
        Tcn[tid] = make_float2(c, -s);
        Tsc[tid] = make_float2(s,  c);
    }
    // Phase 1: Y = conj(q)*k
    for (int i = tid; i < FREQ; i += 256) {
        float ar = qRe[oq + i], ai = qIm[oq + i];
        float br = qRe[ok + i], bi = qIm[ok + i];
        y2[i] = make_float2(ar*br + ai*bi, ar*bi - ai*br);
    }
    __syncthreads();

    // Phase 2: inverse along kh: y2 -> u2
    {
        const int kwg = tid & 7;
        const int hg  = tid >> 3;
        ull acc0[4] = {0,0,0,0};
        ull acc1[4] = {0,0,0,0};
        int idx = 0;
        #pragma unroll 4
        for (int kh = 0; kh < 64; kh++) {
            int idx2 = idx ^ ((kh & 1) << 5);
            ull Ta1 = lds_u64(&Tcs[idx]);
            ull Ta2 = lds_u64(&Tns[idx]);
            ull Tb1 = lds_u64(&Tcs[idx2]);
            ull Tb2 = lds_u64(&Tns[idx2]);
            #pragma unroll
            for (int j = 0; j < 4; j++) {
                float2 y = y2[kh*WR + 4*kwg + j];
                ull yr = dup2(y.x), yi = dup2(y.y);
                fma2(acc0[j], yr, Ta1); fma2(acc0[j], yi, Ta2);
                fma2(acc1[j], yr, Tb1); fma2(acc1[j], yi, Tb2);
            }
            idx = (idx + hg) & 63;
        }
        float2 tmp0[4], tmp1[4];
        #pragma unroll
        for (int j = 0; j < 4; j++) { tmp0[j] = upk2(acc0[j]); tmp1[j] = upk2(acc1[j]); }
        // Nyquist column kw=32
        float2 ny = make_float2(0.f, 0.f);
        if (tid < 64) {
            const int h = tid;
            int ix = 0;
            #pragma unroll 8
            for (int kh = 0; kh < 64; kh++) {
                float2 T = Tcs[ix];
                float2 y = y2[kh*WR + 32];
                ny.x = fmaf(y.x, T.x, fmaf(-y.y, T.y, ny.x));
                ny.y = fmaf(y.x, T.y, fmaf( y.y, T.x, ny.y));
                ix = (ix + h) & 63;
            }
        }
        #pragma unroll
        for (int j = 0; j < 4; j++) {
            u2[hg*WR + 4*kwg + j]        = tmp0[j];
            u2[(hg + 32)*WR + 4*kwg + j] = tmp1[j];
        }
        if (tid < 64) u2[tid*WR + 32] = ny;
    }
    __syncthreads();

    // Phase 3: inverse along kw (Hermitian) -> real plane pl (stride 65), *1/64
    {
        const int wg = tid & 7;
        const int hg = tid >> 3;
        const float scale = 1.0f / 64.0f;
        float accP[2][4] = {{0,0,0,0},{0,0,0,0}};
        float accM[2][4] = {{0,0,0,0},{0,0,0,0}};
        int idx[4], stp[4];
        #pragma unroll
        for (int j = 0; j < 4; j++) { stp[j] = 4*wg + j; idx[j] = stp[j]; }
        float res[2][8];
        #pragma unroll 2
        for (int kw = 1; kw < 32; kw++) {
            float sgn = (kw & 1) ? -1.f : 1.f;
            float2 ua = u2[hg*WR + kw];
            float2 ub = u2[(hg + 32)*WR + kw];
            #pragma unroll
            for (int j = 0; j < 4; j++) {
                float2 T = Tcs[idx[j]];
                float ta = fmaf(ua.x, T.x, -ua.y * T.y);
                float tb = fmaf(ub.x, T.x, -ub.y * T.y);
                accP[0][j] += ta;  accM[0][j] = fmaf(sgn, ta, accM[0][j]);
                accP[1][j] += tb;  accM[1][j] = fmaf(sgn, tb, accM[1][j]);
                idx[j] = (idx[j] + stp[j]) & 63;
            }
        }
        float dcA = u2[hg*WR].x,        nyA = u2[hg*WR + 32].x;
        float dcB = u2[(hg + 32)*WR].x, nyB = u2[(hg + 32)*WR + 32].x;
        #pragma unroll
        for (int j = 0; j < 4; j++) {
            float ps = (j & 1) ? -1.f : 1.f;
            float baseA = fmaf(ps, nyA, dcA);
            float baseB = fmaf(ps, nyB, dcB);
            res[0][j]     = (2.f*accP[0][j] + baseA) * scale;
            res[0][j + 4] = (2.f*accM[0][j] + baseA) * scale;
            res[1][j]     = (2.f*accP[1][j] + baseB) * scale;
            res[1][j + 4] = (2.f*accM[1][j] + baseB) * scale;
        }
        __syncthreads();   // all y2 reads done before pl overwrite
        #pragma unroll
        for (int j = 0; j < 4; j++) {
            int w = 4*wg + j;
            pl[hg*65 + w]             = res[0][j];
            pl[hg*65 + w + 32]        = res[0][j + 4];
            pl[(hg + 32)*65 + w]      = res[1][j];
            pl[(hg + 32)*65 + w + 32] = res[1][j + 4];
        }
    }
    __syncthreads();

    // Phase 4: softmax over the 4096 plane values (stride-65 layout)
    {
        float m = -3.4e38f;
        for (int i = tid; i < NPIX; i += 256) {
            float v = pl[(i >> 6)*65 + (i & 63)];
            m = fmaxf(m, v);
        }
        red[tid] = m; __syncthreads();
        for (int s = 128; s > 0; s >>= 1) { if (tid < s) red[tid] = fmaxf(red[tid], red[tid + s]); __syncthreads(); }
        const float M = red[0];
        __syncthreads();
        float sum = 0.f;
        for (int i = tid; i < NPIX; i += 256) {
            int a = (i >> 6)*65 + (i & 63);
            float e = __expf(pl[a] - M);
            pl[a] = e; sum += e;
        }
        red[tid] = sum; __syncthreads();
        for (int s = 128; s > 0; s >>= 1) { if (tid < s) red[tid] += red[tid + s]; __syncthreads(); }
        const float inv = 1.f / red[0];
        __syncthreads();
        for (int i = tid; i < NPIX; i += 256) {
            int a = (i >> 6)*65 + (i & 63);
            pl[a] *= inv;
        }
    }
    __syncthreads();

    // Phase 5: forward rfft along w: pl -> t2 (=u2)
    {
        const int hg  = tid & 31;
        const int kwg = tid >> 5;
        ull acc0[4] = {0,0,0,0};
        ull acc1[4] = {0,0,0,0};
        int idx[4], stp[4];
        #pragma unroll
        for (int j = 0; j < 4; j++) { idx[j] = 0; stp[j] = 4*kwg + j; }
        #pragma unroll 4
        for (int w = 0; w < 64; w++) {
            ull v0 = dup2(pl[hg*65 + w]);
            ull v1 = dup2(pl[(hg + 32)*65 + w]);
            #pragma unroll
            for (int j = 0; j < 4; j++) {
                ull T = lds_u64(&Tcn[idx[j]]);
                fma2(acc0[j], v0, T);
                fma2(acc1[j], v1, T);
                idx[j] = (idx[j] + stp[j]) & 63;
            }
        }
        float ny = 0.f;
        if (tid < 64) {
            #pragma unroll 8
            for (int w = 0; w < 64; w += 2) ny += pl[tid*65 + w] - pl[tid*65 + w + 1];
        }
        __syncthreads();   // u2 reads from phase 3 done before overwrite
        #pragma unroll
        for (int j = 0; j < 4; j++) {
            u2[hg*WR + 4*kwg + j]        = upk2(acc0[j]);
            u2[(hg + 32)*WR + 4*kwg + j] = upk2(acc1[j]);
        }
        if (tid < 64) u2[tid*WR + 32] = make_float2(ny, 0.f);
    }
    __syncthreads();

    // Phase 6: forward fft along h: t2(=u2) -> global (scale 1, backward norm)
    {
        const int kwg = tid & 7;
        const int khg = tid >> 3;
        ull acc0[4] = {0,0,0,0};
        ull acc1[4] = {0,0,0,0};
        int idx = 0;
        #pragma unroll 4
        for (int h = 0; h < 64; h++) {
            int idx2 = idx ^ ((h & 1) << 5);
            ull Ta1 = lds_u64(&Tcn[idx]);
            ull Ta2 = lds_u64(&Tsc[idx]);
            ull Tb1 = lds_u64(&Tcn[idx2]);
            ull Tb2 = lds_u64(&Tsc[idx2]);
            #pragma unroll
            for (int j = 0; j < 4; j++) {
                float2 u = u2[h*WR + 4*kwg + j];
                ull ud = dup2(u.x), vd = dup2(u.y);
                fma2(acc0[j], ud, Ta1); fma2(acc0[j], vd, Ta2);
                fma2(acc1[j], ud, Tb1); fma2(acc1[j], vd, Tb2);
            }
            idx = (idx + khg) & 63;
        }
        const size_t base = (size_t)plane * FREQ;
        #pragma unroll
        for (int j = 0; j < 4; j++) {
            float2 r0 = upk2(acc0[j]);
            float2 r1 = upk2(acc1[j]);
            int n = 4*kwg + j;
            outre[base + khg*WR + n]      = r0.x;
            outim[base + khg*WR + n]      = r0.y;
            outre[base + (khg+32)*WR + n] = r1.x;
            outim[base + (khg+32)*WR + n] = r1.y;
        }
        if (tid < 64) {
            const int kh = tid;
            float yr = 0.f, yi = 0.f;
            int ix = 0;
            #pragma unroll 8
            for (int h = 0; h < 64; h++) {
                float2 T = Tcn[ix];
                float tr = u2[h*WR + 32].x;
                yr = fmaf(tr, T.x, yr);
                yi = fmaf(tr, T.y, yi);
                ix = (ix + kh) & 63;
            }
            outre[base + kh*WR + 32] = yr;
            outim[base + kh*WR + 32] = yi;
        }
    }
}

// ============================================================
// Fused: Y = conj(a)*b, irfft2(Y), multiply by gate, write plane.
// ============================================================
__global__ __launch_bounds__(256) void prod_ifft2_gate_kernel(
    const float* __restrict__ aRe, const float* __restrict__ aIm,
    int aCPB, int aOff,
    const float* __restrict__ bRe, const float* __restrict__ bIm,
    int bCPB, int bOff,
    const float* __restrict__ gate,
    float* __restrict__ out, float scale)
{
    __shared__ float2 y2[FREQ];
    __shared__ float2 u2[FREQ];
    __shared__ float2 TI1f[64];       // {cos,  sin}
    __shared__ float2 TI2f[64];       // {-sin, cos}
    const int tid = threadIdx.x;
    const int plane = blockIdx.x;
    const int b  = plane >> 9;
    const int ch = plane & 511;
    const size_t oa = ((size_t)b * aCPB + aOff + ch) * FREQ;
    const size_t ob = ((size_t)b * bCPB + bOff + ch) * FREQ;

    if (tid < 64) {
        float s, c; sincosf(TWO_PI_OVER_64 * (float)tid, &s, &c);
        TI1f[tid] = make_float2(c,  s);
        TI2f[tid] = make_float2(-s, c);
    }
    for (int i = tid; i < FREQ; i += 256) {
        float ar = aRe[oa + i], ai = aIm[oa + i];
        float br = bRe[ob + i], bi = bIm[ob + i];
        y2[i] = make_float2(ar*br + ai*bi, ar*bi - ai*br);
    }
    __syncthreads();

    // Stage A: inverse along kh
    {
        const int kwg = tid & 7;
        const int hg  = tid >> 3;
        ull acc0[4] = {0,0,0,0};
        ull acc1[4] = {0,0,0,0};
        int idx = 0;
        #pragma unroll 4
        for (int kh = 0; kh < 64; kh++) {
            int idx2 = idx ^ ((kh & 1) << 5);
            ull Ta1 = lds_u64(&TI1f[idx]);
            ull Ta2 = lds_u64(&TI2f[idx]);
            ull Tb1 = lds_u64(&TI1f[idx2]);
            ull Tb2 = lds_u64(&TI2f[idx2]);
            #pragma unroll
            for (int j = 0; j < 4; j++) {
                float2 y = y2[kh*WR + 4*kwg + j];
                ull yr = dup2(y.x), yi = dup2(y.y);
                fma2(acc0[j], yr, Ta1); fma2(acc0[j], yi, Ta2);
                fma2(acc1[j], yr, Tb1); fma2(acc1[j], yi, Tb2);
            }
            idx = (idx + hg) & 63;
        }
        #pragma unroll
        for (int j = 0; j < 4; j++) {
            u2[hg*WR + 4*kwg + j]        = upk2(acc0[j]);
            u2[(hg + 32)*WR + 4*kwg + j] = upk2(acc1[j]);
        }
        if (tid < 64) {
            const int h = tid;
            float ur = 0.f, ui = 0.f;
            int ix = 0;
            #pragma unroll 8
            for (int kh = 0; kh < 64; kh++) {
                float2 T = TI1f[ix];
                float2 y = y2[kh*WR + 32];
                ur = fmaf(y.x, T.x, fmaf(-y.y, T.y, ur));
                ui = fmaf(y.x, T.y, fmaf( y.y, T.x, ui));
                ix = (ix + h) & 63;
            }
            u2[h*WR + 32] = make_float2(ur, ui);
        }
    }
    __syncthreads();

    // Stage B: inverse along kw (Hermitian), gate-multiply, store
    {
        const int wg = tid & 7;
        const int hg = tid >> 3;
        float accP[2][4] = {{0,0,0,0},{0,0,0,0}};
        float accM[2][4] = {{0,0,0,0},{0,0,0,0}};
        int idx[4], stp[4];
        #pragma unroll
        for (int j = 0; j < 4; j++) { stp[j] = 4*wg + j; idx[j] = stp[j]; }
        #pragma unroll 2
        for (int kw = 1; kw < 32; kw++) {
            float sgn = (kw & 1) ? -1.f : 1.f;
            float2 ua = u2[hg*WR + kw];
            float2 ub = u2[(hg + 32)*WR + kw];
            #pragma unroll
            for (int j = 0; j < 4; j++) {
                float2 T = TI1f[idx[j]];
                float ta = fmaf(ua.x, T.x, -ua.y * T.y);
                float tb = fmaf(ub.x, T.x, -ub.y * T.y);
                accP[0][j] += ta;  accM[0][j] = fmaf(sgn, ta, accM[0][j]);
                accP[1][j] += tb;  accM[1][j] = fmaf(sgn, tb, accM[1][j]);
                idx[j] = (idx[j] + stp[j]) & 63;
            }
        }
        float* op = out + (size_t)plane * NPIX;
        const float* gp = gate + (size_t)plane * NPIX;
        float dcA = u2[hg*WR].x,        nyA = u2[hg*WR + 32].x;
        float dcB = u2[(hg + 32)*WR].x, nyB = u2[(hg + 32)*WR + 32].x;
        #pragma unroll
        for (int j = 0; j < 4; j++) {
            int w = 4*wg + j;
            float ps = (j & 1) ? -1.f : 1.f;
            float baseA = fmaf(ps, nyA, dcA);
            float baseB = fmaf(ps, nyB, dcB);
            op[hg*64 + w]             = (2.f*accP[0][j] + baseA) * scale * gp[hg*64 + w];
            op[hg*64 + w + 32]        = (2.f*accM[0][j] + baseA) * scale * gp[hg*64 + w + 32];
            op[(hg + 32)*64 + w]      = (2.f*accP[1][j] + baseB) * scale * gp[(hg + 32)*64 + w];
            op[(hg + 32)*64 + w + 32] = (2.f*accM[1][j] + baseB) * scale * gp[(hg + 32)*64 + w + 32];
        }
    }
}

// ============================================================
// Packed-f32x2 GEMM, double-buffered (cp.async B, reg-staged A).
// C[m,n] = sum_k A[m,k]*B[k,n]; 128x128x16 tiles, 256 thr, 2 CTA/SM.
// MODE 0: plain. MODE 1: bias + SiLU. MODE 3: bias.
// ============================================================
template<int MODE>
__global__ __launch_bounds__(256, 2) void gemm_kernel(
    const float* __restrict__ A,
    const float* __restrict__ B,
    const float* __restrict__ bias,
    float* __restrict__ C,
    int M, int Ntot, int K)
{
    __shared__ __align__(16) float As[2][16][132];
    __shared__ __align__(16) float Bs[2][16][128];
    const int bx = blockIdx.x, by = blockIdx.y, bz = blockIdx.z;
    const float* Bp = B + (size_t)bz * K * Ntot;
    float* Cp = C + (size_t)bz * M * Ntot;
    const int tid = threadIdx.x;
    const int n0 = bx * 128, m0 = by * 128;
    const int tx = tid & 15, ty = tid >> 4;

    const int arow = tid >> 2;            // 0..63
    const int acol = (tid & 3) * 4;       // 0,4,8,12

    const unsigned int sBs = (unsigned int)__cvta_generic_to_shared(&Bs[0][0][0]);

    // B tile cp.async: 512 16B-chunks per stage, 2 per thread
    auto loadB = [&](int k0, int bufI) {
        #pragma unroll
        for (int q = 0; q < 2; q++) {
            int c   = tid + q * 256;
            int row = c >> 5;
            int col = (c & 31) * 4;
            int n   = n0 + col;
            int sz  = (n + 4 <= Ntot) ? 16 : 0;
            const float* g = Bp + (size_t)(k0 + row) * Ntot + (sz ? n : 0);
            cp_async16(sBs + (unsigned int)(((bufI * 16 + row) * 128 + col) * 4), g, sz);
        }
        cp_commit();
    };

    float4 Ar0, Ar1;
    auto loadA = [&](int k0) {
        Ar0 = *(const float4*)&A[(size_t)(m0 + arow) * K + k0 + acol];
        Ar1 = *(const float4*)&A[(size_t)(m0 + arow + 64) * K + k0 + acol];
    };
    auto storeA = [&](int bufI) {
        As[bufI][acol + 0][arow]      = Ar0.x;
        As[bufI][acol + 1][arow]      = Ar0.y;
        As[bufI][acol + 2][arow]      = Ar0.z;
        As[bufI][acol + 3][arow]      = Ar0.w;
        As[bufI][acol + 0][arow + 64] = Ar1.x;
        As[bufI][acol + 1][arow + 64] = Ar1.y;
        As[bufI][acol + 2][arow + 64] = Ar1.z;
        As[bufI][acol + 3][arow + 64] = Ar1.w;
    };

    ull acc[8][4];
    #pragma unroll
    for (int i = 0; i < 8; i++)
        #pragma unroll
        for (int j = 0; j < 4; j++) acc[i][j] = 0ull;

    const int nStages = K >> 4;

    // prologue: stage 0
    loadA(0);
    loadB(0, 0);
    storeA(0);
    cp_wait0();
    __syncthreads();

    for (int s = 0; s < nStages; s++) {
        const int buf = s & 1, nxt = buf ^ 1;
        const bool more = (s + 1 < nStages);
        if (more) {
            loadA((s + 1) << 4);
            loadB((s + 1) << 4, nxt);
        }
        #pragma unroll
        for (int kk = 0; kk < 16; kk++) {
            ulonglong2 b01 = *(const ulonglong2*)&Bs[buf][kk][4 * tx];
            ulonglong2 b23 = *(const ulonglong2*)&Bs[buf][kk][64 + 4 * tx];
            float4 a0 = *(const float4*)&As[buf][kk][4 * ty];
            float4 a1 = *(const float4*)&As[buf][kk][64 + 4 * ty];
            ull bb[4] = {b01.x, b01.y, b23.x, b23.y};
            ull ad[8] = {dup2(a0.x), dup2(a0.y), dup2(a0.z), dup2(a0.w),
                         dup2(a1.x), dup2(a1.y), dup2(a1.z), dup2(a1.w)};
            #pragma unroll
            for (int i = 0; i < 8; i++)
                #pragma unroll
                for (int j = 0; j < 4; j++)
                    fma2(acc[i][j], ad[i], bb[j]);
        }
        if (more) {
            storeA(nxt);
            cp_wait0();
        }
        __syncthreads();
    }

    #pragma unroll
    for (int i = 0; i < 8; i++) {
        int m = m0 + ((i < 4) ? (ty * 4 + i) : (64 + ty * 4 + i - 4));
        float bv = (MODE >= 1) ? bias[m] : 0.f;
        #pragma unroll
        for (int jp = 0; jp < 4; jp++) {
            float2 v2 = upk2(acc[i][jp]);
            int nbase = n0 + ((jp < 2) ? (tx * 4 + 2 * jp) : (64 + tx * 4 + 2 * (jp - 2)));
            float vx = v2.x + bv, vy = v2.y + bv;
            if (MODE == 1) {
                vx = vx / (1.f + __expf(-vx));
                vy = vy / (1.f + __expf(-vy));
            }
            if (nbase + 1 < Ntot) {
                *(float2*)&Cp[(size_t)m * Ntot + nbase] = make_float2(vx, vy);
            } else if (nbase < Ntot) {
                Cp[(size_t)m * Ntot + nbase] = vx;
            }
        }
    }
}

// ============================================================
extern "C" void kernel_launch(void* const* d_in, const int* in_sizes, int n_in,
                              void* d_out, int out_size)
{
    const float* x      = (const float*)d_in[0];
    const float* w_qkv  = (const float*)d_in[1];
    const float* w_gate = (const float*)d_in[2];
    const float* b_gate = (const float*)d_in[3];
    const float* w_proj = (const float*)d_in[4];
    const float* b_proj = (const float*)d_in[5];
    float* out = (float*)d_out;

    float *Xre, *Xim, *Qre, *Qim, *ybuf, *t;
    cudaGetSymbolAddress((void**)&Xre,  g_Xre);
    cudaGetSymbolAddress((void**)&Xim,  g_Xim);
    cudaGetSymbolAddress((void**)&Qre,  g_Qre);
    cudaGetSymbolAddress((void**)&Qim,  g_Qim);
    cudaGetSymbolAddress((void**)&ybuf, g_y);
    cudaGetSymbolAddress((void**)&t,    g_t);

    const float inv64 = 1.0f / 64.0f;

    // 1. gate: t = SiLU(Wg * x + bg)
    {
        dim3 g(NPIX / 128, CH / 128, BATCH);
        gemm_kernel<1><<<g, 256>>>(w_gate, x, b_gate, t, CH, NPIX, CH);
    }
    // 2. X = rfft2(x), ortho
    fft2_fwd_kernel<<<PLANES, 256>>>(x, Xre, Xim, inv64);
    // 3. QKV = Wqkv * X (re, im)
    {
        dim3 g((FREQ + 127) / 128, CH3 / 128, BATCH);
        gemm_kernel<0><<<g, 256>>>(w_qkv, Xre, nullptr, Qre, CH3, FREQ, CH);
        gemm_kernel<0><<<g, 256>>>(w_qkv, Xim, nullptr, Qim, CH3, FREQ, CH);
    }
    // 4-6. fused: conj(q)*k -> irfft2(ortho) -> softmax -> rfft2(bwd) -> X bufs
    mid_fused_kernel<<<PLANES, 256>>>(Qre, Qim, Xre, Xim);
    // 7. y = irfft2(conj(A)*v) * t, ortho
    prod_ifft2_gate_kernel<<<PLANES, 256>>>(Xre, Xim, CH, 0,
                                            Qre, Qim, CH3, 1024,
                                            t, ybuf, inv64);
    // 8. out = Wp * y + bp
    {
        dim3 g(NPIX / 128, CH / 128, BATCH);
        gemm_kernel<3><<<g, 256>>>(w_proj, ybuf, b_proj, out, CH, NPIX, CH);
    }
}